// round 4
// baseline (speedup 1.0000x reference)
#include <cuda_runtime.h>
#include <math.h>

// Problem constants (fixed by the reference)
//  B=4, L=1024, H=512, NH=8, HD=64, rel rows = 2L = 2048

__device__ float g_rel[2048 * 64];            // rel[t][d], t = 0..2047 (pos = t - 1024)
__device__ float g_q[4 * 8 * 1024 * 64];      // q projected, layout [b][n][l][d]
__device__ float g_v[4 * 8 * 1024 * 64];      // v projected, layout [b][n][l][d]

// ---------------------------------------------------------------------------
// Kernel 1: rel[t][d] = emb(t) @ w_r_w + w_r_b
// emb(t)[h] = h<256 ? sin(pos*freq[h]) : cos(pos*freq[h-256]), pos = t-1024
// freq[c] = exp(c * (-log(1e4)/255)) in fp32 (matches jax weak-typed scalar)
// sin/cos of the fp32 angle evaluated in double for exact range reduction.
// ---------------------------------------------------------------------------
__global__ void rel_kernel(const float* __restrict__ w_r_w,
                           const float* __restrict__ w_r_b) {
    __shared__ float emb[512];
    const int r = blockIdx.x;            // 0..2047
    const int tid = threadIdx.x;         // 64 threads
    const float pos = (float)(r - 1024);
    const float c = (float)(-9.210340371976184 / 255.0);   // -ln(10000)/255 in fp32

    for (int h = tid; h < 512; h += 64) {
        int t = (h < 256) ? h : (h - 256);
        float f = expf((float)t * c);
        float ang = pos * f;             // fp32 product, same as reference
        double a = (double)ang;
        emb[h] = (h < 256) ? (float)sin(a) : (float)cos(a);
    }
    __syncthreads();

    float sum = w_r_b[tid];
    #pragma unroll 8
    for (int h = 0; h < 512; h++)
        sum = fmaf(emb[h], w_r_w[h * 64 + tid], sum);
    g_rel[r * 64 + tid] = sum;
}

// ---------------------------------------------------------------------------
// Kernel 2: projections q = query@Wq + bq, v = value@Wv + bv
// Output stored transposed: out[((b*8 + n)*1024 + l)*64 + d]
// Tiled SGEMM: BM=BN=64, BK=16, 256 threads, 4x4 per-thread tile.
// grid = (8, 64, 2): x = n (64-col tile == one head), y = 64-row tile, z = q/v
// ---------------------------------------------------------------------------
__global__ void __launch_bounds__(256) proj_kernel(
    const float* __restrict__ q_in, const float* __restrict__ v_in,
    const float* __restrict__ wq, const float* __restrict__ bq,
    const float* __restrict__ wv, const float* __restrict__ bv) {

    const float* X;  const float* W;  const float* bias;  float* out;
    if (blockIdx.z == 0) { X = q_in; W = wq; bias = bq; out = g_q; }
    else                 { X = v_in; W = wv; bias = bv; out = g_v; }

    __shared__ float As[64][16];
    __shared__ float Bs[16][64];

    const int tid = threadIdx.x;
    const int tx = tid & 15, ty = tid >> 4;
    const int m0 = blockIdx.y * 64;
    const int n0 = blockIdx.x * 64;

    float acc[4][4] = {};

    for (int k0 = 0; k0 < 512; k0 += 16) {
        float4 av = *(const float4*)&X[(size_t)(m0 + (tid >> 2)) * 512 + k0 + (tid & 3) * 4];
        *(float4*)&As[tid >> 2][(tid & 3) * 4] = av;
        float4 bv4 = *(const float4*)&W[(size_t)(k0 + (tid >> 4)) * 512 + n0 + (tid & 15) * 4];
        *(float4*)&Bs[tid >> 4][(tid & 15) * 4] = bv4;
        __syncthreads();

        #pragma unroll
        for (int kk = 0; kk < 16; kk++) {
            float a[4];
            #pragma unroll
            for (int r = 0; r < 4; r++) a[r] = As[ty * 4 + r][kk];
            float4 b4 = *(const float4*)&Bs[kk][tx * 4];
            float b[4] = { b4.x, b4.y, b4.z, b4.w };
            #pragma unroll
            for (int r = 0; r < 4; r++)
                #pragma unroll
                for (int cc = 0; cc < 4; cc++)
                    acc[r][cc] = fmaf(a[r], b[cc], acc[r][cc]);
        }
        __syncthreads();
    }

    float4 bb = *(const float4*)&bias[n0 + tx * 4];
    const int n = blockIdx.x;
    #pragma unroll
    for (int r = 0; r < 4; r++) {
        int m = m0 + ty * 4 + r;
        int b = m >> 10, l = m & 1023;
        float4 o;
        o.x = acc[r][0] + bb.x;  o.y = acc[r][1] + bb.y;
        o.z = acc[r][2] + bb.z;  o.w = acc[r][3] + bb.w;
        *(float4*)&out[(size_t)((b * 8 + n) * 1024 + l) * 64 + tx * 4] = o;
    }
}

// ---------------------------------------------------------------------------
// Kernel 3: fused attention (flash-style, fp32).
// One block = one (b, n, 64-row i-tile). 256 threads as 16x16 grid, 4x4 frags.
// Per j-tile (64 keys):
//   AC  : QA(64x64) . K(64x64)^T                      (register GEMM)
//   tmpB: QB(64x64) . RBband(127x64)^T -> smem gather  (banded rel GEMM)
//   tmpE: K (64x64) . REband(127x64)^T -> smem gather
//   online softmax, P@V accumulate.
// ---------------------------------------------------------------------------
__global__ void __launch_bounds__(256) attn_kernel(
    const float* __restrict__ key,
    const float* __restrict__ r_r_bias,
    const float* __restrict__ r_w_bias,
    const int*   __restrict__ seq_len_p,
    float* __restrict__ out) {

    extern __shared__ float sm[];
    float* QA  = sm;                 // 64 x 65
    float* QB  = QA + 64 * 65;       // 64 x 65
    float* Ks  = QB + 64 * 65;       // 64 x 65
    float* Pm  = Ks + 64 * 65;       // 64 x 65
    float* RB  = Pm + 64 * 65;       // 128 x 65 (rows 0..126 used)
    float* RE  = RB + 128 * 65;      // 128 x 65
    float* Vs  = RE + 128 * 65;      // 64 x 64
    float* TMP = Vs + 64 * 64;       // 64 x 128

    const int tid = threadIdx.x;
    const int tx = tid & 15, ty = tid >> 4;
    const int tx4 = tx * 4, ty4 = ty * 4;
    const int i0 = blockIdx.x * 64;
    const int bn = blockIdx.y;
    const int b = bn >> 3, n = bn & 7;
    const int seq = *seq_len_p;

    const float* qptr = g_q + (size_t)bn * 1024 * 64;
    const float* vptr = g_v + (size_t)bn * 1024 * 64;
    const float* kptr = key + (size_t)b * 1024 * 512 + n * 64;

    // Load QA = q + r_r_bias, QB = q + r_w_bias (stride-65 smem)
    for (int idx = tid; idx < 1024; idx += 256) {
        int i = idx >> 4; int d4 = (idx & 15) << 2;
        float4 q4 = *(const float4*)&qptr[(size_t)(i0 + i) * 64 + d4];
        float4 rr = *(const float4*)&r_r_bias[n * 64 + d4];
        float4 rw = *(const float4*)&r_w_bias[n * 64 + d4];
        float* pa = &QA[i * 65 + d4];
        pa[0] = q4.x + rr.x; pa[1] = q4.y + rr.y; pa[2] = q4.z + rr.z; pa[3] = q4.w + rr.w;
        float* pb = &QB[i * 65 + d4];
        pb[0] = q4.x + rw.x; pb[1] = q4.y + rw.y; pb[2] = q4.z + rw.z; pb[3] = q4.w + rw.w;
    }

    float m_r[4], l_r[4], acc[4][4];
    #pragma unroll
    for (int r = 0; r < 4; r++) {
        m_r[r] = -INFINITY; l_r[r] = 0.f;
        acc[r][0] = acc[r][1] = acc[r][2] = acc[r][3] = 0.f;
    }

    for (int jt = 0; jt < 16; jt++) {
        const int j0 = jt * 64;
        __syncthreads();   // prev PV done (and QA/QB ready on first iter)

        // --- tile loads ---
        for (int idx = tid; idx < 1024; idx += 256) {
            int j = idx >> 4; int d4 = (idx & 15) << 2;
            float4 k4 = *(const float4*)&kptr[(size_t)(j0 + j) * 512 + d4];
            float* pk = &Ks[j * 65 + d4];
            pk[0] = k4.x; pk[1] = k4.y; pk[2] = k4.z; pk[3] = k4.w;
            float4 v4 = *(const float4*)&vptr[(size_t)(j0 + j) * 64 + d4];
            *(float4*)&Vs[j * 64 + d4] = v4;
        }
        const int rbBase = 1024 + j0 - i0 - 63;   // rel row for (j-i) = jb+c-ib-r maps to u = .. + 63
        const int reBase = 1024 + i0 - j0 - 63;
        for (int idx = tid; idx < 2048; idx += 256) {
            int u = idx >> 4; int d4 = (idx & 15) << 2;
            int rb_r = rbBase + u; if (rb_r > 2047) rb_r = 2047;  // row u=127 never gathered
            int re_r = reBase + u; if (re_r > 2047) re_r = 2047;
            float4 b4 = *(const float4*)&g_rel[(size_t)rb_r * 64 + d4];
            float* prb = &RB[u * 65 + d4];
            prb[0] = b4.x; prb[1] = b4.y; prb[2] = b4.z; prb[3] = b4.w;
            float4 e4 = *(const float4*)&g_rel[(size_t)re_r * 64 + d4];
            float* pre = &RE[u * 65 + d4];
            pre[0] = e4.x; pre[1] = e4.y; pre[2] = e4.z; pre[3] = e4.w;
        }
        __syncthreads();

        // --- AC GEMM: s += QA . Ks^T ---
        float s[4][4] = {};
        {
            const float* qa = &QA[ty4 * 65];
            const float* kk = &Ks[tx4 * 65];
            #pragma unroll 8
            for (int d = 0; d < 64; d++) {
                float a[4], k[4];
                #pragma unroll
                for (int r = 0; r < 4; r++) a[r] = qa[r * 65 + d];
                #pragma unroll
                for (int c = 0; c < 4; c++) k[c] = kk[c * 65 + d];
                #pragma unroll
                for (int r = 0; r < 4; r++)
                    #pragma unroll
                    for (int c = 0; c < 4; c++)
                        s[r][c] = fmaf(a[r], k[c], s[r][c]);
            }
        }

        // --- tmpB = QB . RBband^T (64 x 128) ---
        {
            float tb[4][8] = {};
            const float* qb = &QB[ty4 * 65];
            #pragma unroll 4
            for (int d = 0; d < 64; d++) {
                float a[4], rb[8];
                #pragma unroll
                for (int r = 0; r < 4; r++) a[r] = qb[r * 65 + d];
                #pragma unroll
                for (int u = 0; u < 8; u++) rb[u] = RB[(tx + 16 * u) * 65 + d];
                #pragma unroll
                for (int r = 0; r < 4; r++)
                    #pragma unroll
                    for (int u = 0; u < 8; u++)
                        tb[r][u] = fmaf(a[r], rb[u], tb[r][u]);
            }
            #pragma unroll
            for (int r = 0; r < 4; r++)
                #pragma unroll
                for (int u = 0; u < 8; u++)
                    TMP[(ty4 + r) * 128 + tx + 16 * u] = tb[r][u];
        }
        __syncthreads();

        // gather B: s[r][c] += tmpB[i', (j'-i')+63]
        #pragma unroll
        for (int r = 0; r < 4; r++)
            #pragma unroll
            for (int c = 0; c < 4; c++)
                s[r][c] += TMP[(ty4 + r) * 128 + (tx4 + c) - (ty4 + r) + 63];
        __syncthreads();

        // --- tmpE = Ks . REband^T (64 x 128) ---
        {
            float te[4][8] = {};
            const float* kk = &Ks[ty4 * 65];
            #pragma unroll 4
            for (int d = 0; d < 64; d++) {
                float a[4], re[8];
                #pragma unroll
                for (int r = 0; r < 4; r++) a[r] = kk[r * 65 + d];
                #pragma unroll
                for (int u = 0; u < 8; u++) re[u] = RE[(tx + 16 * u) * 65 + d];
                #pragma unroll
                for (int r = 0; r < 4; r++)
                    #pragma unroll
                    for (int u = 0; u < 8; u++)
                        te[r][u] = fmaf(a[r], re[u], te[r][u]);
            }
            #pragma unroll
            for (int r = 0; r < 4; r++)
                #pragma unroll
                for (int u = 0; u < 8; u++)
                    TMP[(ty4 + r) * 128 + tx + 16 * u] = te[r][u];
        }
        __syncthreads();

        // gather E: s[r][c] += tmpE[j', (i'-j')+63]
        #pragma unroll
        for (int r = 0; r < 4; r++)
            #pragma unroll
            for (int c = 0; c < 4; c++)
                s[r][c] += TMP[(tx4 + c) * 128 + (ty4 + r) - (tx4 + c) + 63];

        // --- mask + online softmax ---
        #pragma unroll
        for (int c = 0; c < 4; c++) {
            if (j0 + tx4 + c >= seq) {
                s[0][c] = -1e30f; s[1][c] = -1e30f; s[2][c] = -1e30f; s[3][c] = -1e30f;
            }
        }
        #pragma unroll
        for (int r = 0; r < 4; r++) {
            float mr = fmaxf(fmaxf(s[r][0], s[r][1]), fmaxf(s[r][2], s[r][3]));
            mr = fmaxf(mr, __shfl_xor_sync(0xffffffffu, mr, 1));
            mr = fmaxf(mr, __shfl_xor_sync(0xffffffffu, mr, 2));
            mr = fmaxf(mr, __shfl_xor_sync(0xffffffffu, mr, 4));
            mr = fmaxf(mr, __shfl_xor_sync(0xffffffffu, mr, 8));
            float mnew = fmaxf(m_r[r], mr);
            float scale = __expf(m_r[r] - mnew);
            float psum = 0.f;
            #pragma unroll
            for (int c = 0; c < 4; c++) {
                float p = __expf(s[r][c] - mnew);
                Pm[(ty4 + r) * 65 + tx4 + c] = p;
                psum += p;
            }
            psum += __shfl_xor_sync(0xffffffffu, psum, 1);
            psum += __shfl_xor_sync(0xffffffffu, psum, 2);
            psum += __shfl_xor_sync(0xffffffffu, psum, 4);
            psum += __shfl_xor_sync(0xffffffffu, psum, 8);
            l_r[r] = l_r[r] * scale + psum;
            m_r[r] = mnew;
            acc[r][0] *= scale; acc[r][1] *= scale; acc[r][2] *= scale; acc[r][3] *= scale;
        }
        __syncthreads();

        // --- PV: acc += P . Vs ---
        #pragma unroll 4
        for (int jj = 0; jj < 64; jj++) {
            float4 v4 = *(const float4*)&Vs[jj * 64 + tx4];
            #pragma unroll
            for (int r = 0; r < 4; r++) {
                float p = Pm[(ty4 + r) * 65 + jj];
                acc[r][0] = fmaf(p, v4.x, acc[r][0]);
                acc[r][1] = fmaf(p, v4.y, acc[r][1]);
                acc[r][2] = fmaf(p, v4.z, acc[r][2]);
                acc[r][3] = fmaf(p, v4.w, acc[r][3]);
            }
        }
    }

    // epilogue: out[b][i][n*64+d] = acc / l
    #pragma unroll
    for (int r = 0; r < 4; r++) {
        float inv = 1.0f / l_r[r];
        int row = i0 + ty4 + r;
        float4 o;
        o.x = acc[r][0] * inv; o.y = acc[r][1] * inv;
        o.z = acc[r][2] * inv; o.w = acc[r][3] * inv;
        *(float4*)&out[(size_t)(b * 1024 + row) * 512 + n * 64 + tx4] = o;
    }
}

// ---------------------------------------------------------------------------
extern "C" void kernel_launch(void* const* d_in, const int* in_sizes, int n_in,
                              void* d_out, int out_size) {
    const float* query    = (const float*)d_in[0];
    const float* key      = (const float*)d_in[1];
    const float* value    = (const float*)d_in[2];
    const float* w_q_w    = (const float*)d_in[3];
    const float* w_q_b    = (const float*)d_in[4];
    const float* w_v_w    = (const float*)d_in[5];
    const float* w_v_b    = (const float*)d_in[6];
    const float* w_r_w    = (const float*)d_in[7];
    const float* w_r_b    = (const float*)d_in[8];
    const float* r_r_bias = (const float*)d_in[9];
    const float* r_w_bias = (const float*)d_in[10];
    const int*   seq_len  = (const int*)d_in[11];
    float* out = (float*)d_out;

    rel_kernel<<<2048, 64>>>(w_r_w, w_r_b);
    proj_kernel<<<dim3(8, 64, 2), 256>>>(query, value, w_q_w, w_q_b, w_v_w, w_v_b);

    const int smem_bytes = (4 * 64 * 65 + 2 * 128 * 65 + 64 * 64 + 64 * 128) * 4; // 182272
    cudaFuncSetAttribute(attn_kernel, cudaFuncAttributeMaxDynamicSharedMemorySize, smem_bytes);
    attn_kernel<<<dim3(16, 32), 256, smem_bytes>>>(key, r_r_bias, r_w_bias, seq_len, out);
}

// round 5
// speedup vs baseline: 1.1549x; 1.1549x over previous
#include <cuda_runtime.h>
#include <math.h>

// Problem constants (fixed by the reference)
//  B=4, L=1024, H=512, NH=8, HD=64, rel rows = 2L = 2048

__device__ float g_rel[2048 * 64];            // rel[t][d], t = 0..2047 (pos = t - 1024)
__device__ float g_q[4 * 8 * 1024 * 64];      // q projected, layout [b][n][l][d]
__device__ float g_v[4 * 8 * 1024 * 64];      // v projected, layout [b][n][l][d]

// ---------------------------------------------------------------------------
// Kernel 1: rel[t][d] = emb(t) @ w_r_w + w_r_b
// 256 blocks x 256 threads; each block does 8 rows with W cached in smem.
// fp32 sinf/cosf (reference is fp32 jax sin; tolerance 1e-3, we sit at ~1e-5).
// ---------------------------------------------------------------------------
__global__ void __launch_bounds__(256) rel_kernel(const float* __restrict__ w_r_w,
                                                  const float* __restrict__ w_r_b) {
    extern __shared__ float rsm[];
    float* Wsm = rsm;            // 512*64 = 32768 floats
    float* Emb = Wsm + 32768;    // 8*512  =  4096 floats

    const int tid = threadIdx.x;
    const int r0 = blockIdx.x * 8;
    const float cc = (float)(-9.210340371976184 / 255.0);   // -ln(10000)/255

    for (int idx = tid * 4; idx < 32768; idx += 1024)
        *(float4*)&Wsm[idx] = *(const float4*)&w_r_w[idx];

    for (int idx = tid; idx < 8 * 512; idx += 256) {
        int row = idx >> 9;
        int h = idx & 511;
        int t = (h < 256) ? h : (h - 256);
        float f = expf((float)t * cc);
        float ang = (float)(r0 + row - 1024) * f;
        Emb[idx] = (h < 256) ? sinf(ang) : cosf(ang);
    }
    __syncthreads();

    const int d = tid & 63;
    const int rl = tid >> 6;
    const float bias = w_r_b[d];
    #pragma unroll
    for (int rr = 0; rr < 2; rr++) {
        int row = rl + 4 * rr;
        float sum = bias;
        const float* e = &Emb[row * 512];
        #pragma unroll 8
        for (int h = 0; h < 512; h++)
            sum = fmaf(e[h], Wsm[h * 64 + d], sum);
        g_rel[(size_t)(r0 + row) * 64 + d] = sum;
    }
}

// ---------------------------------------------------------------------------
// Kernel 2: projections q = query@Wq + bq, v = value@Wv + bv  (unchanged)
// ---------------------------------------------------------------------------
__global__ void __launch_bounds__(256) proj_kernel(
    const float* __restrict__ q_in, const float* __restrict__ v_in,
    const float* __restrict__ wq, const float* __restrict__ bq,
    const float* __restrict__ wv, const float* __restrict__ bv) {

    const float* X;  const float* W;  const float* bias;  float* out;
    if (blockIdx.z == 0) { X = q_in; W = wq; bias = bq; out = g_q; }
    else                 { X = v_in; W = wv; bias = bv; out = g_v; }

    __shared__ float As[64][16];
    __shared__ float Bs[16][64];

    const int tid = threadIdx.x;
    const int tx = tid & 15, ty = tid >> 4;
    const int m0 = blockIdx.y * 64;
    const int n0 = blockIdx.x * 64;

    float acc[4][4] = {};

    for (int k0 = 0; k0 < 512; k0 += 16) {
        float4 av = *(const float4*)&X[(size_t)(m0 + (tid >> 2)) * 512 + k0 + (tid & 3) * 4];
        *(float4*)&As[tid >> 2][(tid & 3) * 4] = av;
        float4 bv4 = *(const float4*)&W[(size_t)(k0 + (tid >> 4)) * 512 + n0 + (tid & 15) * 4];
        *(float4*)&Bs[tid >> 4][(tid & 15) * 4] = bv4;
        __syncthreads();

        #pragma unroll
        for (int kk = 0; kk < 16; kk++) {
            float a[4];
            #pragma unroll
            for (int r = 0; r < 4; r++) a[r] = As[ty * 4 + r][kk];
            float4 b4 = *(const float4*)&Bs[kk][tx * 4];
            float b[4] = { b4.x, b4.y, b4.z, b4.w };
            #pragma unroll
            for (int r = 0; r < 4; r++)
                #pragma unroll
                for (int cc = 0; cc < 4; cc++)
                    acc[r][cc] = fmaf(a[r], b[cc], acc[r][cc]);
        }
        __syncthreads();
    }

    float4 bb = *(const float4*)&bias[n0 + tx * 4];
    const int n = blockIdx.x;
    #pragma unroll
    for (int r = 0; r < 4; r++) {
        int m = m0 + ty * 4 + r;
        int b = m >> 10, l = m & 1023;
        float4 o;
        o.x = acc[r][0] + bb.x;  o.y = acc[r][1] + bb.y;
        o.z = acc[r][2] + bb.z;  o.w = acc[r][3] + bb.w;
        *(float4*)&out[(size_t)((b * 8 + n) * 1024 + l) * 64 + tx * 4] = o;
    }
}

// ---------------------------------------------------------------------------
// Kernel 3: fused attention, fp32, direct-band score computation.
// One block = one (b, n, 64-row i-tile). 256 threads.
// STRIDED fragment mapping: thread (tx,ty) owns score rows i'=ty+16r,
// cols j'=tx+16c (r,c in 0..3). Band rel rows then index as tx-ty+const,
// which is conflict-free in stride-65 smem.
// Per j-tile, single fused pass:
//   s[r][c] = QA_i.K_j  +  QB_i.rel[1024+j-i]  +  K_j.rel[1024+i-j]
// then online softmax and PV.
// ---------------------------------------------------------------------------
__global__ void __launch_bounds__(256) attn_kernel(
    const float* __restrict__ key,
    const float* __restrict__ r_r_bias,
    const float* __restrict__ r_w_bias,
    const int*   __restrict__ seq_len_p,
    float* __restrict__ out) {

    extern __shared__ float sm[];
    float* QA  = sm;                 // 64 x 65
    float* QB  = QA + 64 * 65;       // 64 x 65
    float* Ks  = QB + 64 * 65;       // 64 x 65
    float* Pm  = Ks + 64 * 65;       // 64 x 65
    float* RB  = Pm + 64 * 65;       // 128 x 65 (rows 0..126 used)
    float* RE  = RB + 128 * 65;      // 128 x 65
    float* Vs  = RE + 128 * 65;      // 64 x 64

    const int tid = threadIdx.x;
    const int tx = tid & 15, ty = tid >> 4;
    const int tx4 = tx * 4;
    const int i0 = blockIdx.x * 64;
    const int bn = blockIdx.y;
    const int b = bn >> 3, n = bn & 7;
    const int seq = *seq_len_p;

    const float* qptr = g_q + (size_t)bn * 1024 * 64;
    const float* vptr = g_v + (size_t)bn * 1024 * 64;
    const float* kptr = key + (size_t)b * 1024 * 512 + n * 64;

    // Load QA = q + r_r_bias, QB = q + r_w_bias (stride-65 smem)
    for (int idx = tid; idx < 1024; idx += 256) {
        int i = idx >> 4; int d4 = (idx & 15) << 2;
        float4 q4 = *(const float4*)&qptr[(size_t)(i0 + i) * 64 + d4];
        float4 rr = *(const float4*)&r_r_bias[n * 64 + d4];
        float4 rw = *(const float4*)&r_w_bias[n * 64 + d4];
        float* pa = &QA[i * 65 + d4];
        pa[0] = q4.x + rr.x; pa[1] = q4.y + rr.y; pa[2] = q4.z + rr.z; pa[3] = q4.w + rr.w;
        float* pb = &QB[i * 65 + d4];
        pb[0] = q4.x + rw.x; pb[1] = q4.y + rw.y; pb[2] = q4.z + rw.z; pb[3] = q4.w + rw.w;
    }

    float m_r[4], l_r[4], acc[4][4];
    #pragma unroll
    for (int r = 0; r < 4; r++) {
        m_r[r] = -INFINITY; l_r[r] = 0.f;
        acc[r][0] = acc[r][1] = acc[r][2] = acc[r][3] = 0.f;
    }

    // Per-thread band bases (rel row = base + 16*(c-r) for B, +16*(r-c) for E)
    const int baseB = tx - ty + 63;   // in [48, 78]; +/-48 -> [0,126]
    const int baseE = ty - tx + 63;

    const float* pQA = QA + ty * 65;
    const float* pQB = QB + ty * 65;
    const float* pK  = Ks + tx * 65;
    const float* pRB = RB + baseB * 65;
    const float* pRE = RE + baseE * 65;

    for (int jt = 0; jt < 16; jt++) {
        const int j0 = jt * 64;
        __syncthreads();   // prev PV done reading Pm/Vs; first iter: QA/QB ready

        // --- tile loads ---
        for (int idx = tid; idx < 1024; idx += 256) {
            int j = idx >> 4; int d4 = (idx & 15) << 2;
            float4 k4 = *(const float4*)&kptr[(size_t)(j0 + j) * 512 + d4];
            float* pk = &Ks[j * 65 + d4];
            pk[0] = k4.x; pk[1] = k4.y; pk[2] = k4.z; pk[3] = k4.w;
            float4 v4 = *(const float4*)&vptr[(size_t)(j0 + j) * 64 + d4];
            *(float4*)&Vs[j * 64 + d4] = v4;
        }
        const int rbBase = 1024 + j0 - i0 - 63;   // rel row for u=0
        const int reBase = 1024 + i0 - j0 - 63;
        for (int idx = tid; idx < 2048; idx += 256) {
            int u = idx >> 4; int d4 = (idx & 15) << 2;
            int rb_r = rbBase + u; if (rb_r > 2047) rb_r = 2047;  // row u=127 unused
            int re_r = reBase + u; if (re_r > 2047) re_r = 2047;
            float4 b4 = *(const float4*)&g_rel[(size_t)rb_r * 64 + d4];
            float* prb = &RB[u * 65 + d4];
            prb[0] = b4.x; prb[1] = b4.y; prb[2] = b4.z; prb[3] = b4.w;
            float4 e4 = *(const float4*)&g_rel[(size_t)re_r * 64 + d4];
            float* pre = &RE[u * 65 + d4];
            pre[0] = e4.x; pre[1] = e4.y; pre[2] = e4.z; pre[3] = e4.w;
        }
        __syncthreads();

        // --- fused AC + B + E score pass ---
        float s[4][4] = {};
        #pragma unroll 4
        for (int d = 0; d < 64; d++) {
            float qa[4], qb[4], k[4];
            #pragma unroll
            for (int r = 0; r < 4; r++) {
                qa[r] = pQA[r * (16 * 65) + d];
                qb[r] = pQB[r * (16 * 65) + d];
            }
            #pragma unroll
            for (int c = 0; c < 4; c++) k[c] = pK[c * (16 * 65) + d];
            float rb[7], re[7];
            #pragma unroll
            for (int m = 0; m < 7; m++) {
                rb[m] = pRB[(m - 3) * (16 * 65) + d];
                re[m] = pRE[(m - 3) * (16 * 65) + d];
            }
            #pragma unroll
            for (int r = 0; r < 4; r++)
                #pragma unroll
                for (int c = 0; c < 4; c++) {
                    float t = fmaf(qa[r], k[c], s[r][c]);
                    t = fmaf(qb[r], rb[c - r + 3], t);
                    s[r][c] = fmaf(k[c], re[r - c + 3], t);
                }
        }

        // --- mask + online softmax ---
        #pragma unroll
        for (int c = 0; c < 4; c++) {
            if (j0 + tx + 16 * c >= seq) {
                s[0][c] = -1e30f; s[1][c] = -1e30f; s[2][c] = -1e30f; s[3][c] = -1e30f;
            }
        }
        #pragma unroll
        for (int r = 0; r < 4; r++) {
            float mr = fmaxf(fmaxf(s[r][0], s[r][1]), fmaxf(s[r][2], s[r][3]));
            mr = fmaxf(mr, __shfl_xor_sync(0xffffffffu, mr, 1));
            mr = fmaxf(mr, __shfl_xor_sync(0xffffffffu, mr, 2));
            mr = fmaxf(mr, __shfl_xor_sync(0xffffffffu, mr, 4));
            mr = fmaxf(mr, __shfl_xor_sync(0xffffffffu, mr, 8));
            float mnew = fmaxf(m_r[r], mr);
            float scale = __expf(m_r[r] - mnew);
            float psum = 0.f;
            float* prow = &Pm[(ty + 16 * r) * 65 + tx];
            #pragma unroll
            for (int c = 0; c < 4; c++) {
                float p = __expf(s[r][c] - mnew);
                prow[16 * c] = p;
                psum += p;
            }
            psum += __shfl_xor_sync(0xffffffffu, psum, 1);
            psum += __shfl_xor_sync(0xffffffffu, psum, 2);
            psum += __shfl_xor_sync(0xffffffffu, psum, 4);
            psum += __shfl_xor_sync(0xffffffffu, psum, 8);
            l_r[r] = l_r[r] * scale + psum;
            m_r[r] = mnew;
            acc[r][0] *= scale; acc[r][1] *= scale; acc[r][2] *= scale; acc[r][3] *= scale;
        }
        __syncthreads();

        // --- PV: acc += P . Vs  (acc col c holds head-dim tx4+c) ---
        #pragma unroll 4
        for (int jj = 0; jj < 64; jj++) {
            float4 v4 = *(const float4*)&Vs[jj * 64 + tx4];
            #pragma unroll
            for (int r = 0; r < 4; r++) {
                float p = Pm[(ty + 16 * r) * 65 + jj];
                acc[r][0] = fmaf(p, v4.x, acc[r][0]);
                acc[r][1] = fmaf(p, v4.y, acc[r][1]);
                acc[r][2] = fmaf(p, v4.z, acc[r][2]);
                acc[r][3] = fmaf(p, v4.w, acc[r][3]);
            }
        }
    }

    // epilogue: out[b][i][n*64+d] = acc / l   (rows i0 + ty + 16r)
    #pragma unroll
    for (int r = 0; r < 4; r++) {
        float inv = 1.0f / l_r[r];
        int row = i0 + ty + 16 * r;
        float4 o;
        o.x = acc[r][0] * inv; o.y = acc[r][1] * inv;
        o.z = acc[r][2] * inv; o.w = acc[r][3] * inv;
        *(float4*)&out[(size_t)(b * 1024 + row) * 512 + n * 64 + tx4] = o;
    }
}

// ---------------------------------------------------------------------------
extern "C" void kernel_launch(void* const* d_in, const int* in_sizes, int n_in,
                              void* d_out, int out_size) {
    const float* query    = (const float*)d_in[0];
    const float* key      = (const float*)d_in[1];
    const float* value    = (const float*)d_in[2];
    const float* w_q_w    = (const float*)d_in[3];
    const float* w_q_b    = (const float*)d_in[4];
    const float* w_v_w    = (const float*)d_in[5];
    const float* w_v_b    = (const float*)d_in[6];
    const float* w_r_w    = (const float*)d_in[7];
    const float* w_r_b    = (const float*)d_in[8];
    const float* r_r_bias = (const float*)d_in[9];
    const float* r_w_bias = (const float*)d_in[10];
    const int*   seq_len  = (const int*)d_in[11];
    float* out = (float*)d_out;

    const int rel_smem = (32768 + 4096) * 4;   // 147456
    cudaFuncSetAttribute(rel_kernel, cudaFuncAttributeMaxDynamicSharedMemorySize, rel_smem);
    rel_kernel<<<256, 256, rel_smem>>>(w_r_w, w_r_b);

    proj_kernel<<<dim3(8, 64, 2), 256>>>(query, value, w_q_w, w_q_b, w_v_w, w_v_b);

    const int attn_smem = (4 * 64 * 65 + 2 * 128 * 65 + 64 * 64) * 4;   // 149504
    cudaFuncSetAttribute(attn_kernel, cudaFuncAttributeMaxDynamicSharedMemorySize, attn_smem);
    attn_kernel<<<dim3(16, 32), 256, attn_smem>>>(key, r_r_bias, r_w_bias, seq_len, out);
}